// round 12
// baseline (speedup 1.0000x reference)
#include <cuda_runtime.h>
#include <cstdint>

// Voxelization: per-point voxel coords.
//   input : points [N, 4] float32 (x, y, z, feat)
//   output: [3, N] float32, rows = (z, y, x); -1.0f for out-of-range points.
//
// R12 = R7 structure (PPT=4, default stores) + __ldcs on the point loads.
// Rationale: ncu shows only ~172 MB DRAM traffic/iter (reads 128 MB + ~44 MB
// write evictions); the 96 MB output buffer is partially L2-resident across
// graph replays. Evict-first READS keep the output fully resident, removing
// the write-eviction traffic. (R6 tested evict-first STORES — the exactly
// wrong direction — and regressed; loads were never tested unconfounded.)

#define VSX 0.05f
#define VSY 0.05f
#define VSZ 0.1f
#define MINX 0.0f
#define MINY -40.0f
#define MINZ -3.0f
#define GXF 1408.0f
#define GYF 1600.0f
#define GZF 40.0f

__device__ __forceinline__ void voxel_coord(const float4 p, float& cx, float& cy, float& cz) {
    // IEEE round-to-nearest division to exactly match the fp32 reference
    // (0.05f is not exactly representable; mul-by-reciprocal would flip boundary voxels).
    const float fx = floorf(__fdiv_rn(p.x - MINX, VSX));
    const float fy = floorf(__fdiv_rn(p.y - MINY, VSY));
    const float fz = floorf(__fdiv_rn(p.z - MINZ, VSZ));
    const bool valid = (fx >= 0.0f) & (fx < GXF) &
                       (fy >= 0.0f) & (fy < GYF) &
                       (fz >= 0.0f) & (fz < GZF);
    cx = valid ? fx : -1.0f;
    cy = valid ? fy : -1.0f;
    cz = valid ? fz : -1.0f;
}

__global__ __launch_bounds__(256)
void voxelize_kernel(const float4* __restrict__ pts,
                     float* __restrict__ out,   // [3, N]: z row, y row, x row
                     unsigned int n) {
    const unsigned int g = blockIdx.x * blockDim.x + threadIdx.x;
    const unsigned int base = g << 2;   // 4 points per thread; 3*n < 2^31 fits u32
    if (base >= n) return;

    float* __restrict__ out_z = out;
    float* __restrict__ out_y = out + n;
    float* __restrict__ out_x = out + 2u * n;

    if (base + 3u < n) {
        // Vector path: 4 x LDG.E.128.CS in (evict-first: pure stream, protect
        // L2-resident output buffer), 3 x STG.128 out (default policy).
        const float4 p0 = __ldcs(pts + base + 0u);
        const float4 p1 = __ldcs(pts + base + 1u);
        const float4 p2 = __ldcs(pts + base + 2u);
        const float4 p3 = __ldcs(pts + base + 3u);

        float4 vz, vy, vx;
        voxel_coord(p0, vx.x, vy.x, vz.x);
        voxel_coord(p1, vx.y, vy.y, vz.y);
        voxel_coord(p2, vx.z, vy.z, vz.z);
        voxel_coord(p3, vx.w, vy.w, vz.w);

        *reinterpret_cast<float4*>(out_z + base) = vz;
        *reinterpret_cast<float4*>(out_y + base) = vy;
        *reinterpret_cast<float4*>(out_x + base) = vx;
    } else {
        // Scalar tail (only hit if n % 4 != 0).
        for (unsigned int i = base; i < n; ++i) {
            const float4 p = pts[i];
            float cx, cy, cz;
            voxel_coord(p, cx, cy, cz);
            out_z[i] = cz;
            out_y[i] = cy;
            out_x[i] = cx;
        }
    }
}

extern "C" void kernel_launch(void* const* d_in, const int* in_sizes, int n_in,
                              void* d_out, int out_size) {
    const float4* pts = (const float4*)d_in[0];
    float* out = (float*)d_out;
    const unsigned int n = (unsigned int)(in_sizes[0] / 4);   // points are [N, 4] floats

    const unsigned int n_groups = (n + 3u) / 4u;   // 4 points per thread
    const unsigned int threads = 256u;
    const unsigned int blocks = (n_groups + threads - 1u) / threads;
    voxelize_kernel<<<blocks, threads>>>(pts, out, n);
}

// round 13
// speedup vs baseline: 1.0608x; 1.0608x over previous
#include <cuda_runtime.h>
#include <cstdint>

// Voxelization: per-point voxel coords.  FINAL (converged).
//   input : points [N, 4] float32 (x, y, z, feat)
//   output: [3, N] float32, rows = (z, y, x); -1.0f for out-of-range points.
//
// Constants (must match the fp32 reference exactly):
//   voxel_size = (0.05, 0.05, 0.1)
//   pc_range mins = (0.0, -40.0, -3.0)
//   grid = (1408, 1600, 40)
//
// Converged config, all alternatives measured and rejected:
//   PPT=8            -> L1tex wavefront-queue overflow, -11%
//   __stcs stores    -> L1tex cost, -6%
//   __ldcs loads     -> no traffic reduction, -3%
//   PPT=4, u32 idx, default cache policy -> 29.0us kernel, DRAM 75%,
//   ~5.9 TB/s sustained DRAM throughput (reads 128 MB compulsory + write
//   evictions; remainder of writes L2-resident across graph replays).

#define VSX 0.05f
#define VSY 0.05f
#define VSZ 0.1f
#define MINX 0.0f
#define MINY -40.0f
#define MINZ -3.0f
#define GXF 1408.0f
#define GYF 1600.0f
#define GZF 40.0f

__device__ __forceinline__ void voxel_coord(const float4 p, float& cx, float& cy, float& cz) {
    // IEEE round-to-nearest division to exactly match the fp32 reference
    // (0.05f is not exactly representable; mul-by-reciprocal would flip boundary voxels).
    const float fx = floorf(__fdiv_rn(p.x - MINX, VSX));
    const float fy = floorf(__fdiv_rn(p.y - MINY, VSY));
    const float fz = floorf(__fdiv_rn(p.z - MINZ, VSZ));
    const bool valid = (fx >= 0.0f) & (fx < GXF) &
                       (fy >= 0.0f) & (fy < GYF) &
                       (fz >= 0.0f) & (fz < GZF);
    cx = valid ? fx : -1.0f;
    cy = valid ? fy : -1.0f;
    cz = valid ? fz : -1.0f;
}

__global__ __launch_bounds__(256)
void voxelize_kernel(const float4* __restrict__ pts,
                     float* __restrict__ out,   // [3, N]: z row, y row, x row
                     unsigned int n) {
    const unsigned int g = blockIdx.x * blockDim.x + threadIdx.x;
    const unsigned int base = g << 2;   // 4 points per thread; 3*n < 2^31 fits u32
    if (base >= n) return;

    float* __restrict__ out_z = out;
    float* __restrict__ out_y = out + n;
    float* __restrict__ out_x = out + 2u * n;

    if (base + 3u < n) {
        // Vector path: 4 x LDG.128 in, 3 x STG.128 out (default cache policy).
        const float4 p0 = pts[base + 0u];
        const float4 p1 = pts[base + 1u];
        const float4 p2 = pts[base + 2u];
        const float4 p3 = pts[base + 3u];

        float4 vz, vy, vx;
        voxel_coord(p0, vx.x, vy.x, vz.x);
        voxel_coord(p1, vx.y, vy.y, vz.y);
        voxel_coord(p2, vx.z, vy.z, vz.z);
        voxel_coord(p3, vx.w, vy.w, vz.w);

        *reinterpret_cast<float4*>(out_z + base) = vz;
        *reinterpret_cast<float4*>(out_y + base) = vy;
        *reinterpret_cast<float4*>(out_x + base) = vx;
    } else {
        // Scalar tail (only hit if n % 4 != 0).
        for (unsigned int i = base; i < n; ++i) {
            const float4 p = pts[i];
            float cx, cy, cz;
            voxel_coord(p, cx, cy, cz);
            out_z[i] = cz;
            out_y[i] = cy;
            out_x[i] = cx;
        }
    }
}

extern "C" void kernel_launch(void* const* d_in, const int* in_sizes, int n_in,
                              void* d_out, int out_size) {
    const float4* pts = (const float4*)d_in[0];
    float* out = (float*)d_out;
    const unsigned int n = (unsigned int)(in_sizes[0] / 4);   // points are [N, 4] floats

    const unsigned int n_groups = (n + 3u) / 4u;   // 4 points per thread
    const unsigned int threads = 256u;
    const unsigned int blocks = (n_groups + threads - 1u) / threads;
    voxelize_kernel<<<blocks, threads>>>(pts, out, n);
}

// round 14
// speedup vs baseline: 1.0617x; 1.0009x over previous
#include <cuda_runtime.h>
#include <cstdint>

// Voxelization: per-point voxel coords.
//   input : points [N, 4] float32 (x, y, z, feat)
//   output: [3, N] float32, rows = (z, y, x); -1.0f for out-of-range points.
//
// Constants (must match the fp32 reference exactly):
//   voxel_size = (0.05, 0.05, 0.1)
//   pc_range mins = (0.0, -40.0, -3.0)
//   grid = (1408, 1600, 40)
//
// Converged memory structure (PPT=4, default cache policy, u32 indexing):
// measured 29.0-29.2us kernel, DRAM ~75% (mixed R/W turnaround ceiling).
// Rejected by measurement: PPT=8 (-11%), __stcs stores (-6%), __ldcs loads (-3%).
// This round's single delta: 512-thread blocks (halve CTA count / wave count;
// identical per-thread instruction stream). Expected neutral to -0.5us.

#define VSX 0.05f
#define VSY 0.05f
#define VSZ 0.1f
#define MINX 0.0f
#define MINY -40.0f
#define MINZ -3.0f
#define GXF 1408.0f
#define GYF 1600.0f
#define GZF 40.0f

__device__ __forceinline__ void voxel_coord(const float4 p, float& cx, float& cy, float& cz) {
    // IEEE round-to-nearest division to exactly match the fp32 reference
    // (0.05f is not exactly representable; mul-by-reciprocal would flip boundary voxels).
    const float fx = floorf(__fdiv_rn(p.x - MINX, VSX));
    const float fy = floorf(__fdiv_rn(p.y - MINY, VSY));
    const float fz = floorf(__fdiv_rn(p.z - MINZ, VSZ));
    const bool valid = (fx >= 0.0f) & (fx < GXF) &
                       (fy >= 0.0f) & (fy < GYF) &
                       (fz >= 0.0f) & (fz < GZF);
    cx = valid ? fx : -1.0f;
    cy = valid ? fy : -1.0f;
    cz = valid ? fz : -1.0f;
}

__global__ __launch_bounds__(512)
void voxelize_kernel(const float4* __restrict__ pts,
                     float* __restrict__ out,   // [3, N]: z row, y row, x row
                     unsigned int n) {
    const unsigned int g = blockIdx.x * blockDim.x + threadIdx.x;
    const unsigned int base = g << 2;   // 4 points per thread; 3*n < 2^31 fits u32
    if (base >= n) return;

    float* __restrict__ out_z = out;
    float* __restrict__ out_y = out + n;
    float* __restrict__ out_x = out + 2u * n;

    if (base + 3u < n) {
        // Vector path: 4 x LDG.128 in, 3 x STG.128 out (default cache policy).
        const float4 p0 = pts[base + 0u];
        const float4 p1 = pts[base + 1u];
        const float4 p2 = pts[base + 2u];
        const float4 p3 = pts[base + 3u];

        float4 vz, vy, vx;
        voxel_coord(p0, vx.x, vy.x, vz.x);
        voxel_coord(p1, vx.y, vy.y, vz.y);
        voxel_coord(p2, vx.z, vy.z, vz.z);
        voxel_coord(p3, vx.w, vy.w, vz.w);

        *reinterpret_cast<float4*>(out_z + base) = vz;
        *reinterpret_cast<float4*>(out_y + base) = vy;
        *reinterpret_cast<float4*>(out_x + base) = vx;
    } else {
        // Scalar tail (only hit if n % 4 != 0).
        for (unsigned int i = base; i < n; ++i) {
            const float4 p = pts[i];
            float cx, cy, cz;
            voxel_coord(p, cx, cy, cz);
            out_z[i] = cz;
            out_y[i] = cy;
            out_x[i] = cx;
        }
    }
}

extern "C" void kernel_launch(void* const* d_in, const int* in_sizes, int n_in,
                              void* d_out, int out_size) {
    const float4* pts = (const float4*)d_in[0];
    float* out = (float*)d_out;
    const unsigned int n = (unsigned int)(in_sizes[0] / 4);   // points are [N, 4] floats

    const unsigned int n_groups = (n + 3u) / 4u;   // 4 points per thread
    const unsigned int threads = 512u;
    const unsigned int blocks = (n_groups + threads - 1u) / threads;
    voxelize_kernel<<<blocks, threads>>>(pts, out, n);
}